// round 1
// baseline (speedup 1.0000x reference)
#include <cuda_runtime.h>

// Problem constants (fixed by the dataset)
#define B_    1024
#define T_    8
#define BT_   8192      // B*T
#define IN_   4096
#define OUT_  4096
#define R_    64

// Scratch (no cudaMalloc allowed): W1 [t][k][l], v [bt][l]
__device__ float g_W1[T_ * R_ * R_];
__device__ float g_v[BT_ * R_];

// ---------- packed f32x2 helpers (sm_100+: FFMA2) ----------
__device__ __forceinline__ unsigned long long pk2(float lo, float hi) {
    unsigned long long r;
    asm("mov.b64 %0, {%1, %2};" : "=l"(r) : "f"(lo), "f"(hi));
    return r;
}
__device__ __forceinline__ void upk2(unsigned long long v, float& lo, float& hi) {
    asm("mov.b64 {%0, %1}, %2;" : "=f"(lo), "=f"(hi) : "l"(v));
}
__device__ __forceinline__ unsigned long long ffma2(unsigned long long a,
                                                    unsigned long long b,
                                                    unsigned long long c) {
    unsigned long long d;
    asm("fma.rn.f32x2 %0, %1, %2, %3;" : "=l"(d) : "l"(a), "l"(b), "l"(c));
    return d;
}

// ---------------------------------------------------------------------------
// Kernel 1: W1[t,k,l] = sum_j task[t,j] * tc[j,k,l]    (tiny)
// grid (R_, T_), block R_ : t=by, k=bx, l=tid
// ---------------------------------------------------------------------------
__global__ void k_w1(const float* __restrict__ task, const float* __restrict__ tc) {
    int t = blockIdx.y, k = blockIdx.x, l = threadIdx.x;
    float acc = 0.f;
#pragma unroll 8
    for (int j = 0; j < R_; j++)
        acc += task[t * R_ + j] * tc[(j * R_ + k) * R_ + l];
    g_W1[(t * R_ + k) * R_ + l] = acc;
}

// ---------------------------------------------------------------------------
// Kernel 2 (fused): u = x @ in_core  (M=8192, N=64, K=4096), then
//                   v[bt,:] = u[bt,:] @ W1[bt%8]  in the epilogue.
// Block tile: 64 rows x 64 cols, BK=32. 256 threads, 4x4 micro-tile (f32x2).
// grid = BT_/64 = 128 blocks
// ---------------------------------------------------------------------------
#define BM2 64
#define BK2 32
__global__ __launch_bounds__(256) void k_uv(const float* __restrict__ x,
                                            const float* __restrict__ in_core) {
    __shared__ __align__(16) float xst[BK2][BM2 + 1];  // x chunk, transposed [k][m]
    __shared__ __align__(16) float ws[BK2][R_];        // in_core chunk [k][n]
    __shared__ __align__(16) float us[BM2][R_ + 1];    // u tile

    const int m0 = blockIdx.x * BM2;
    const int tid = threadIdx.x;
    const int tx = tid & 15;    // n-group: cols tx*4 .. tx*4+3
    const int ty = tid >> 4;    // m-group: rows ty*4 .. ty*4+3

    unsigned long long acc[4][2];
#pragma unroll
    for (int r = 0; r < 4; r++) { acc[r][0] = 0ull; acc[r][1] = 0ull; }

    for (int kc = 0; kc < IN_; kc += BK2) {
        // load x chunk [64 rows x 32 cols] as float4, transpose into xst
        {
            const int c4 = tid & 7;      // float4 index within a row (32 floats)
            const int row = tid >> 3;    // 0..31
#pragma unroll
            for (int p = 0; p < 2; p++) {
                const int rr = row + p * 32;
                float4 v4 = *(const float4*)&x[(size_t)(m0 + rr) * IN_ + kc + c4 * 4];
                xst[c4 * 4 + 0][rr] = v4.x;
                xst[c4 * 4 + 1][rr] = v4.y;
                xst[c4 * 4 + 2][rr] = v4.z;
                xst[c4 * 4 + 3][rr] = v4.w;
            }
        }
        // load in_core chunk [32 rows x 64 cols], natural layout
        {
            const int c4 = tid & 15;     // 16 float4 per 64-float row
            const int row = tid >> 4;    // 0..15
#pragma unroll
            for (int p = 0; p < 2; p++) {
                const int rr = row + p * 16;
                float4 v4 = *(const float4*)&in_core[(size_t)(kc + rr) * R_ + c4 * 4];
                *(float4*)&ws[rr][c4 * 4] = v4;
            }
        }
        __syncthreads();

#pragma unroll 8
        for (int kk = 0; kk < BK2; kk++) {
            ulonglong2 b = *(const ulonglong2*)&ws[kk][tx * 4];
#pragma unroll
            for (int r = 0; r < 4; r++) {
                float a = xst[kk][ty * 4 + r];
                unsigned long long a2 = pk2(a, a);
                acc[r][0] = ffma2(a2, b.x, acc[r][0]);
                acc[r][1] = ffma2(a2, b.y, acc[r][1]);
            }
        }
        __syncthreads();
    }

    // dump u tile to smem
#pragma unroll
    for (int r = 0; r < 4; r++) {
        float lo, hi;
        upk2(acc[r][0], lo, hi);
        us[ty * 4 + r][tx * 4 + 0] = lo;
        us[ty * 4 + r][tx * 4 + 1] = hi;
        upk2(acc[r][1], lo, hi);
        us[ty * 4 + r][tx * 4 + 2] = lo;
        us[ty * 4 + r][tx * 4 + 3] = hi;
    }
    __syncthreads();

    // v epilogue: thread handles rows { ty + 16q } (all share t = (m0+ty)%8),
    // cols tx*4 .. tx*4+3.  v[row,l] = sum_k u[row,k] * W1[t,k,l]
    const int t = (m0 + ty) & (T_ - 1);
    const float* __restrict__ W1t = &g_W1[t * R_ * R_];
    unsigned long long vacc[4][2];
#pragma unroll
    for (int q = 0; q < 4; q++) { vacc[q][0] = 0ull; vacc[q][1] = 0ull; }

#pragma unroll 4
    for (int k = 0; k < R_; k++) {
        ulonglong2 w = *(const ulonglong2*)&W1t[k * R_ + tx * 4];
#pragma unroll
        for (int q = 0; q < 4; q++) {
            float a = us[ty + 16 * q][k];
            unsigned long long a2 = pk2(a, a);
            vacc[q][0] = ffma2(a2, w.x, vacc[q][0]);
            vacc[q][1] = ffma2(a2, w.y, vacc[q][1]);
        }
    }
#pragma unroll
    for (int q = 0; q < 4; q++) {
        float4 o;
        upk2(vacc[q][0], o.x, o.y);
        upk2(vacc[q][1], o.z, o.w);
        *(float4*)&g_v[(size_t)(m0 + ty + 16 * q) * R_ + tx * 4] = o;
    }
}

// ---------------------------------------------------------------------------
// Kernel 3: y = v @ out_core^T   (M=8192, N=4096, K=64, whole-K in one tile)
// Block tile 64x64, 256 threads, 4x4 micro-tile (f32x2).
// grid (OUT_/64, BT_/64) = (64, 128)
// ---------------------------------------------------------------------------
#define BM4 64
#define BN4 64
__global__ __launch_bounds__(256) void k_y(const float* __restrict__ out_core,
                                           float* __restrict__ y) {
    __shared__ __align__(16) float vst[R_][BM4 + 4];  // v tile transposed [l][row]
    __shared__ __align__(16) float ost[R_][BN4];      // out_core tile transposed [l][col]

    const int n0 = blockIdx.x * BN4;
    const int m0 = blockIdx.y * BM4;
    const int tid = threadIdx.x;
    const int tx = tid & 15;
    const int ty = tid >> 4;

    {
        const int c4 = tid & 15;    // l/4
        const int row = tid >> 4;   // 0..15
#pragma unroll
        for (int p = 0; p < 4; p++) {
            const int rr = row + p * 16;
            float4 v4 = *(const float4*)&g_v[(size_t)(m0 + rr) * R_ + c4 * 4];
            vst[c4 * 4 + 0][rr] = v4.x;
            vst[c4 * 4 + 1][rr] = v4.y;
            vst[c4 * 4 + 2][rr] = v4.z;
            vst[c4 * 4 + 3][rr] = v4.w;
        }
#pragma unroll
        for (int p = 0; p < 4; p++) {
            const int cc = row + p * 16;
            float4 v4 = *(const float4*)&out_core[(size_t)(n0 + cc) * R_ + c4 * 4];
            ost[c4 * 4 + 0][cc] = v4.x;
            ost[c4 * 4 + 1][cc] = v4.y;
            ost[c4 * 4 + 2][cc] = v4.z;
            ost[c4 * 4 + 3][cc] = v4.w;
        }
    }
    __syncthreads();

    unsigned long long acc[4][2];
#pragma unroll
    for (int r = 0; r < 4; r++) { acc[r][0] = 0ull; acc[r][1] = 0ull; }

#pragma unroll 8
    for (int l = 0; l < R_; l++) {
        ulonglong2 b = *(const ulonglong2*)&ost[l][tx * 4];
#pragma unroll
        for (int r = 0; r < 4; r++) {
            float a = vst[l][ty * 4 + r];
            unsigned long long a2 = pk2(a, a);
            acc[r][0] = ffma2(a2, b.x, acc[r][0]);
            acc[r][1] = ffma2(a2, b.y, acc[r][1]);
        }
    }

#pragma unroll
    for (int r = 0; r < 4; r++) {
        float4 o;
        upk2(acc[r][0], o.x, o.y);
        upk2(acc[r][1], o.z, o.w);
        *(float4*)&y[(size_t)(m0 + ty * 4 + r) * OUT_ + n0 + tx * 4] = o;
    }
}

// ---------------------------------------------------------------------------
extern "C" void kernel_launch(void* const* d_in, const int* in_sizes, int n_in,
                              void* d_out, int out_size) {
    const float* x        = (const float*)d_in[0];
    const float* tc       = (const float*)d_in[1];
    const float* task     = (const float*)d_in[2];
    const float* in_core  = (const float*)d_in[3];
    const float* out_core = (const float*)d_in[4];
    float* y = (float*)d_out;

    k_w1<<<dim3(R_, T_), R_>>>(task, tc);
    k_uv<<<BT_ / BM2, 256>>>(x, in_core);
    k_y<<<dim3(OUT_ / BN4, BT_ / BM4), 256>>>(out_core, y);
}

// round 2
// speedup vs baseline: 1.2767x; 1.2767x over previous
#include <cuda_runtime.h>

#define B_    1024
#define T_    8
#define BT_   8192
#define IN_   4096
#define OUT_  4096
#define R_    64

__device__ float g_W1[T_ * R_ * R_];
__device__ float g_v[BT_ * R_];

// ---------- packed f32x2 helpers ----------
typedef unsigned long long u64;
__device__ __forceinline__ u64 pk2(float lo, float hi) {
    u64 r;
    asm("mov.b64 %0, {%1, %2};" : "=l"(r) : "f"(lo), "f"(hi));
    return r;
}
__device__ __forceinline__ void upk2(u64 v, float& lo, float& hi) {
    asm("mov.b64 {%0, %1}, %2;" : "=f"(lo), "=f"(hi) : "l"(v));
}
__device__ __forceinline__ u64 ffma2(u64 a, u64 b, u64 c) {
    u64 d;
    asm("fma.rn.f32x2 %0, %1, %2, %3;" : "=l"(d) : "l"(a), "l"(b), "l"(c));
    return d;
}

// ---------------------------------------------------------------------------
// Kernel 1: W1[t,k,l] = sum_j task[t,j] * tc[j,k,l]
// 128 blocks x 256 threads, one output each, 4 independent partials.
// ---------------------------------------------------------------------------
__global__ __launch_bounds__(256) void k_w1(const float* __restrict__ task,
                                            const float* __restrict__ tc) {
    const int idx = blockIdx.x * 256 + threadIdx.x;   // = t*4096 + k*64 + l
    const int t = idx >> 12;
    const int k = (idx >> 6) & 63;
    const int l = idx & 63;
    float s0 = 0.f, s1 = 0.f, s2 = 0.f, s3 = 0.f;
#pragma unroll 4
    for (int j = 0; j < R_; j += 4) {
        s0 += task[t * R_ + j + 0] * tc[((j + 0) * R_ + k) * R_ + l];
        s1 += task[t * R_ + j + 1] * tc[((j + 1) * R_ + k) * R_ + l];
        s2 += task[t * R_ + j + 2] * tc[((j + 2) * R_ + k) * R_ + l];
        s3 += task[t * R_ + j + 3] * tc[((j + 3) * R_ + k) * R_ + l];
    }
    g_W1[idx] = (s0 + s1) + (s2 + s3);
}

// ---------------------------------------------------------------------------
// Kernel 2 (fused): u = x @ in_core  (64-row tile, single task per block),
// then v = u @ W1[t] from smem.
// Block bx: t = bx&7, g = bx>>3; rows are g*512 + t + 8*r (r = 0..63) so the
// whole block shares one task -> W1[t] fits in smem for the epilogue.
// 256 threads, micro-tile 4x4 (FFMA2, lanes = col pairs).
// ---------------------------------------------------------------------------
#define BK2 32
__global__ __launch_bounds__(256) void k_uv(const float* __restrict__ x,
                                            const float* __restrict__ in_core) {
    __shared__ __align__(16) float xst[BK2][68];      // x chunk transposed [k][m]
    __shared__ __align__(16) float ws[BK2][R_];       // in_core chunk [k][n]
    __shared__ __align__(16) float us[64][R_ + 1];    // u tile
    __shared__ __align__(16) float W1s[R_][R_];       // W1[t]

    const int bx = blockIdx.x;
    const int g = bx >> 3;
    const int t = bx & 7;
    const size_t rowbase = (size_t)g * 512 + t;       // global row = rowbase + 8*r

    const int tid = threadIdx.x;
    const int tx = tid & 15;     // cols tx*4 .. tx*4+3
    const int ty = tid >> 4;     // rows ty*4 .. ty*4+3

    // load W1[t] into smem (16 KB), 4 float4 per thread
    {
        const float* W1t = &g_W1[t * R_ * R_];
        float* W1f = &W1s[0][0];
#pragma unroll
        for (int p = 0; p < 4; p++) {
            const int i = (tid + p * 256) * 4;
            *(float4*)&W1f[i] = *(const float4*)&W1t[i];
        }
    }

    u64 acc[4][2];
#pragma unroll
    for (int r = 0; r < 4; r++) { acc[r][0] = 0ull; acc[r][1] = 0ull; }

    const int xc4 = tid & 7;     // float4 col index in 32-wide chunk
    const int xrow = tid >> 3;   // 0..31
    const int wc4 = tid & 15;
    const int wrow = tid >> 4;   // 0..15

    for (int kc = 0; kc < IN_; kc += BK2) {
        // x chunk [64 rows x 32 k] -> transposed xst
#pragma unroll
        for (int p = 0; p < 2; p++) {
            const int rr = xrow + p * 32;
            float4 v4 = *(const float4*)&x[(rowbase + 8 * (size_t)rr) * IN_ + kc + xc4 * 4];
            xst[xc4 * 4 + 0][rr] = v4.x;
            xst[xc4 * 4 + 1][rr] = v4.y;
            xst[xc4 * 4 + 2][rr] = v4.z;
            xst[xc4 * 4 + 3][rr] = v4.w;
        }
        // in_core chunk [32 k x 64 n], natural
#pragma unroll
        for (int p = 0; p < 2; p++) {
            const int rr = wrow + p * 16;
            *(float4*)&ws[rr][wc4 * 4] =
                *(const float4*)&in_core[(size_t)(kc + rr) * R_ + wc4 * 4];
        }
        __syncthreads();

#pragma unroll 8
        for (int kk = 0; kk < BK2; kk++) {
            float4 a4 = *(const float4*)&xst[kk][ty * 4];
            ulonglong2 b = *(const ulonglong2*)&ws[kk][tx * 4];
            u64 a0 = pk2(a4.x, a4.x), a1 = pk2(a4.y, a4.y);
            u64 a2 = pk2(a4.z, a4.z), a3 = pk2(a4.w, a4.w);
            acc[0][0] = ffma2(a0, b.x, acc[0][0]);
            acc[0][1] = ffma2(a0, b.y, acc[0][1]);
            acc[1][0] = ffma2(a1, b.x, acc[1][0]);
            acc[1][1] = ffma2(a1, b.y, acc[1][1]);
            acc[2][0] = ffma2(a2, b.x, acc[2][0]);
            acc[2][1] = ffma2(a2, b.y, acc[2][1]);
            acc[3][0] = ffma2(a3, b.x, acc[3][0]);
            acc[3][1] = ffma2(a3, b.y, acc[3][1]);
        }
        __syncthreads();
    }

    // dump u tile
#pragma unroll
    for (int r = 0; r < 4; r++) {
        float lo, hi;
        upk2(acc[r][0], lo, hi);
        us[ty * 4 + r][tx * 4 + 0] = lo;
        us[ty * 4 + r][tx * 4 + 1] = hi;
        upk2(acc[r][1], lo, hi);
        us[ty * 4 + r][tx * 4 + 2] = lo;
        us[ty * 4 + r][tx * 4 + 3] = hi;
    }
    __syncthreads();

    // epilogue: v[row,:] = u[row,:] @ W1[t]; thread rows = ty + 16q
    u64 vacc[4][2];
#pragma unroll
    for (int q = 0; q < 4; q++) { vacc[q][0] = 0ull; vacc[q][1] = 0ull; }

#pragma unroll 8
    for (int k = 0; k < R_; k++) {
        ulonglong2 w = *(const ulonglong2*)&W1s[k][tx * 4];
#pragma unroll
        for (int q = 0; q < 4; q++) {
            u64 a2 = pk2(us[ty + 16 * q][k], us[ty + 16 * q][k]);
            vacc[q][0] = ffma2(a2, w.x, vacc[q][0]);
            vacc[q][1] = ffma2(a2, w.y, vacc[q][1]);
        }
    }
#pragma unroll
    for (int q = 0; q < 4; q++) {
        float4 o;
        upk2(vacc[q][0], o.x, o.y);
        upk2(vacc[q][1], o.z, o.w);
        *(float4*)&g_v[(rowbase + 8 * (size_t)(ty + 16 * q)) * R_ + tx * 4] = o;
    }
}

// ---------------------------------------------------------------------------
// Kernel 3: y = v @ out_core^T  (M=8192, N=4096, K=64 in one smem tile)
// Block tile 64x64, 256 threads, micro 4x4 FFMA2.  grid (64, 128).
// ---------------------------------------------------------------------------
__global__ __launch_bounds__(256) void k_y(const float* __restrict__ out_core,
                                           float* __restrict__ y) {
    __shared__ __align__(16) float vst[R_][68];   // v tile transposed [l][row]
    __shared__ __align__(16) float ost[R_][68];   // out_core tile transposed [l][col]

    const int n0 = blockIdx.x * 64;
    const int m0 = blockIdx.y * 64;
    const int tid = threadIdx.x;
    const int tx = tid & 15;
    const int ty = tid >> 4;

    const int c4 = tid & 15;
    const int row = tid >> 4;
#pragma unroll
    for (int p = 0; p < 4; p++) {
        const int rr = row + p * 16;
        float4 v4 = *(const float4*)&g_v[(size_t)(m0 + rr) * R_ + c4 * 4];
        vst[c4 * 4 + 0][rr] = v4.x;
        vst[c4 * 4 + 1][rr] = v4.y;
        vst[c4 * 4 + 2][rr] = v4.z;
        vst[c4 * 4 + 3][rr] = v4.w;
        float4 o4 = *(const float4*)&out_core[(size_t)(n0 + rr) * R_ + c4 * 4];
        ost[c4 * 4 + 0][rr] = o4.x;
        ost[c4 * 4 + 1][rr] = o4.y;
        ost[c4 * 4 + 2][rr] = o4.z;
        ost[c4 * 4 + 3][rr] = o4.w;
    }
    __syncthreads();

    u64 acc[4][2];
#pragma unroll
    for (int r = 0; r < 4; r++) { acc[r][0] = 0ull; acc[r][1] = 0ull; }

#pragma unroll 8
    for (int l = 0; l < R_; l++) {
        float4 a4 = *(const float4*)&vst[l][ty * 4];
        ulonglong2 b = *(const ulonglong2*)&ost[l][tx * 4];
        u64 a0 = pk2(a4.x, a4.x), a1 = pk2(a4.y, a4.y);
        u64 a2 = pk2(a4.z, a4.z), a3 = pk2(a4.w, a4.w);
        acc[0][0] = ffma2(a0, b.x, acc[0][0]);
        acc[0][1] = ffma2(a0, b.y, acc[0][1]);
        acc[1][0] = ffma2(a1, b.x, acc[1][0]);
        acc[1][1] = ffma2(a1, b.y, acc[1][1]);
        acc[2][0] = ffma2(a2, b.x, acc[2][0]);
        acc[2][1] = ffma2(a2, b.y, acc[2][1]);
        acc[3][0] = ffma2(a3, b.x, acc[3][0]);
        acc[3][1] = ffma2(a3, b.y, acc[3][1]);
    }

#pragma unroll
    for (int r = 0; r < 4; r++) {
        float4 o;
        upk2(acc[r][0], o.x, o.y);
        upk2(acc[r][1], o.z, o.w);
        *(float4*)&y[(size_t)(m0 + ty * 4 + r) * OUT_ + n0 + tx * 4] = o;
    }
}

// ---------------------------------------------------------------------------
extern "C" void kernel_launch(void* const* d_in, const int* in_sizes, int n_in,
                              void* d_out, int out_size) {
    const float* x        = (const float*)d_in[0];
    const float* tc       = (const float*)d_in[1];
    const float* task     = (const float*)d_in[2];
    const float* in_core  = (const float*)d_in[3];
    const float* out_core = (const float*)d_in[4];
    float* y = (float*)d_out;

    k_w1<<<128, 256>>>(task, tc);
    k_uv<<<128, 256>>>(x, in_core);
    k_y<<<dim3(OUT_ / 64, BT_ / 64), 256>>>(out_core, y);
}

// round 4
// speedup vs baseline: 1.9672x; 1.5408x over previous
#include <cuda_runtime.h>
#include <cuda_bf16.h>
#include <cstdint>

#define BT_   8192
#define IN_   4096
#define OUT_  4096
#define R_    64
#define T_    8

// ---------------- device scratch ----------------
__device__ float          g_W1[T_ * R_ * R_];
__device__ __nv_bfloat16  g_B1hi[R_ * IN_];     // in_core^T hi  [n=64][k=4096]
__device__ __nv_bfloat16  g_B1lo[R_ * IN_];
__device__ __nv_bfloat16  g_ochi[OUT_ * R_];    // out_core hi   [n=4096][k=64]
__device__ __nv_bfloat16  g_oclo[OUT_ * R_];
__device__ __nv_bfloat16  g_vhi[BT_ * R_];      // v hi          [m=8192][k=64]
__device__ __nv_bfloat16  g_vlo[BT_ * R_];

typedef unsigned long long u64;

// ---------- packed f32x2 (v epilogue) ----------
__device__ __forceinline__ u64 pk2(float lo, float hi) {
    u64 r; asm("mov.b64 %0, {%1, %2};" : "=l"(r) : "f"(lo), "f"(hi)); return r;
}
__device__ __forceinline__ void upk2(u64 v, float& lo, float& hi) {
    asm("mov.b64 {%0, %1}, %2;" : "=f"(lo), "=f"(hi) : "l"(v));
}
__device__ __forceinline__ u64 ffma2(u64 a, u64 b, u64 c) {
    u64 d; asm("fma.rn.f32x2 %0, %1, %2, %3;" : "=l"(d) : "l"(a), "l"(b), "l"(c)); return d;
}

// ---------- fp32 -> bf16 hi/lo split ----------
__device__ __forceinline__ void split4(float4 v, uint32_t& h01, uint32_t& h23,
                                       uint32_t& l01, uint32_t& l23) {
    __nv_bfloat162 h0 = __floats2bfloat162_rn(v.x, v.y);
    __nv_bfloat162 h1 = __floats2bfloat162_rn(v.z, v.w);
    float rx = v.x - __bfloat162float(h0.x);
    float ry = v.y - __bfloat162float(h0.y);
    float rz = v.z - __bfloat162float(h1.x);
    float rw = v.w - __bfloat162float(h1.y);
    __nv_bfloat162 l0 = __floats2bfloat162_rn(rx, ry);
    __nv_bfloat162 l1 = __floats2bfloat162_rn(rz, rw);
    h01 = *(uint32_t*)&h0; h23 = *(uint32_t*)&h1;
    l01 = *(uint32_t*)&l0; l23 = *(uint32_t*)&l1;
}

// ---------- classic tensor-core mma (arch-agnostic, works on sm_103 base) ----
__device__ __forceinline__ void mma_bf16(float* c, const uint32_t* a, const uint32_t* b) {
    asm volatile(
        "mma.sync.aligned.m16n8k16.row.col.f32.bf16.bf16.f32 "
        "{%0,%1,%2,%3}, {%4,%5,%6,%7}, {%8,%9}, {%0,%1,%2,%3};"
        : "+f"(c[0]), "+f"(c[1]), "+f"(c[2]), "+f"(c[3])
        : "r"(a[0]), "r"(a[1]), "r"(a[2]), "r"(a[3]), "r"(b[0]), "r"(b[1]));
}

// ---------------------------------------------------------------------------
// k_prep: W1 (fp32), in_core^T hi/lo, out_core hi/lo.  grid 256 x 256 thr.
// ---------------------------------------------------------------------------
__global__ __launch_bounds__(256) void k_prep(const float* __restrict__ task,
                                              const float* __restrict__ tc,
                                              const float* __restrict__ in_core,
                                              const float* __restrict__ out_core) {
    __shared__ float s[64][68];
    const int bx = blockIdx.x, tid = threadIdx.x;
    if (bx < 64) {
        const int kc = bx * 64;
        const int r = tid >> 2, f = (tid & 3) * 16;
#pragma unroll
        for (int j = 0; j < 16; j += 4)
            *(float4*)&s[r][f + j] = *(const float4*)&in_core[(size_t)(kc + r) * 64 + f + j];
        __syncthreads();
        const int n = tid >> 2, ks = (tid & 3) * 16;
#pragma unroll
        for (int j = 0; j < 16; j += 2) {
            float a = s[ks + j][n], b = s[ks + j + 1][n];
            __nv_bfloat162 h = __floats2bfloat162_rn(a, b);
            __nv_bfloat162 l = __floats2bfloat162_rn(a - __bfloat162float(h.x),
                                                     b - __bfloat162float(h.y));
            *(uint32_t*)&g_B1hi[(size_t)n * IN_ + kc + ks + j] = *(uint32_t*)&h;
            *(uint32_t*)&g_B1lo[(size_t)n * IN_ + kc + ks + j] = *(uint32_t*)&l;
        }
    } else if (bx < 128) {
        const size_t base = (size_t)(bx - 64) * 4096 + (size_t)tid * 16;
#pragma unroll
        for (int j = 0; j < 16; j += 4) {
            float4 v = *(const float4*)&out_core[base + j];
            uint32_t h01, h23, l01, l23;
            split4(v, h01, h23, l01, l23);
            *(uint32_t*)&g_ochi[base + j]     = h01;
            *(uint32_t*)&g_ochi[base + j + 2] = h23;
            *(uint32_t*)&g_oclo[base + j]     = l01;
            *(uint32_t*)&g_oclo[base + j + 2] = l23;
        }
    } else {
        const int idx = (bx - 128) * 256 + tid;
        const int t = idx >> 12, kl = idx & 4095;
        float a0 = 0, a1 = 0, a2 = 0, a3 = 0, a4 = 0, a5 = 0, a6 = 0, a7 = 0;
#pragma unroll
        for (int j = 0; j < 64; j += 8) {
            a0 += task[t * 64 + j + 0] * tc[(size_t)(j + 0) * 4096 + kl];
            a1 += task[t * 64 + j + 1] * tc[(size_t)(j + 1) * 4096 + kl];
            a2 += task[t * 64 + j + 2] * tc[(size_t)(j + 2) * 4096 + kl];
            a3 += task[t * 64 + j + 3] * tc[(size_t)(j + 3) * 4096 + kl];
            a4 += task[t * 64 + j + 4] * tc[(size_t)(j + 4) * 4096 + kl];
            a5 += task[t * 64 + j + 5] * tc[(size_t)(j + 5) * 4096 + kl];
            a6 += task[t * 64 + j + 6] * tc[(size_t)(j + 6) * 4096 + kl];
            a7 += task[t * 64 + j + 7] * tc[(size_t)(j + 7) * 4096 + kl];
        }
        g_W1[idx] = ((a0 + a1) + (a2 + a3)) + ((a4 + a5) + (a6 + a7));
    }
}

// ---------------------------------------------------------------------------
// k_gemm1: u = x @ in_core (tile 64m x 64n, one task per CTA), double-buffered
// K chunks of 64, bf16 hi/lo 3-term mma.sync. Epilogue: v = u @ W1[t] -> split.
// smem map (bytes): AH[2][64][36w]@0, AL@18432, BH@36864, BL@55296, W1@73728.
// ---------------------------------------------------------------------------
#define G1_S     36
#define G1_STAGE 2304   // 64*36 words
#define G1_SMEM  90112

__global__ __launch_bounds__(256) void k_gemm1(const float* __restrict__ x) {
    extern __shared__ char sm[];
    uint32_t* AH = (uint32_t*)sm;
    uint32_t* AL = (uint32_t*)(sm + 18432);
    uint32_t* BH = (uint32_t*)(sm + 36864);
    uint32_t* BL = (uint32_t*)(sm + 55296);
    float*    W1s = (float*)(sm + 73728);
    float*    us  = (float*)sm;              // alias after k-loop: [64][68]

    const int tid = threadIdx.x;
    const int warp = tid >> 5, lane = tid & 31;
    const int gr = lane >> 2, p = lane & 3;
    const int bx = blockIdx.x, t = bx & 7, g = bx >> 3;

    {   // W1[t] -> smem
        const float4* src = (const float4*)(g_W1 + t * 4096);
        float4* dst = (float4*)W1s;
#pragma unroll
        for (int i = 0; i < 4; i++) dst[tid + i * 256] = src[tid + i * 256];
    }

    const int lrow = tid >> 2, lq = tid & 3;
    const float* xrow = x + (size_t)(t + 8 * (g * 64 + lrow)) * IN_;
    const __nv_bfloat16* bsrc_hi = g_B1hi + (size_t)lrow * IN_ + lq * 16;
    const __nv_bfloat16* bsrc_lo = g_B1lo + (size_t)lrow * IN_ + lq * 16;

    const int m0 = (warp >> 1) * 16, n0 = (warp & 1) * 32;

    float acc[4][4];
#pragma unroll
    for (int i = 0; i < 4; i++) acc[i][0] = acc[i][1] = acc[i][2] = acc[i][3] = 0.f;

#define G1_LOAD(s, c) do {                                                    \
    uint32_t* ah = AH + (s) * G1_STAGE + lrow * G1_S;                         \
    uint32_t* al = AL + (s) * G1_STAGE + lrow * G1_S;                         \
    const float* xs = xrow + (c) * 64;                                        \
    _Pragma("unroll")                                                         \
    for (int seg = 0; seg < 4; seg++) {                                       \
        float4 v = *(const float4*)(xs + seg * 16 + lq * 4);                  \
        uint32_t h01, h23, l01, l23;                                          \
        split4(v, h01, h23, l01, l23);                                        \
        *(uint2*)(ah + seg * 8 + lq * 2) = make_uint2(h01, h23);              \
        *(uint2*)(al + seg * 8 + lq * 2) = make_uint2(l01, l23);              \
    }                                                                         \
    uint32_t* bh = BH + (s) * G1_STAGE + lrow * G1_S + lq * 8;                \
    uint32_t* bl = BL + (s) * G1_STAGE + lrow * G1_S + lq * 8;                \
    const uint4* sh = (const uint4*)(bsrc_hi + (size_t)(c) * 64);             \
    const uint4* sl = (const uint4*)(bsrc_lo + (size_t)(c) * 64);             \
    *(uint4*)(bh)     = sh[0]; *(uint4*)(bh + 4) = sh[1];                     \
    *(uint4*)(bl)     = sl[0]; *(uint4*)(bl + 4) = sl[1];                     \
} while (0)

#define G1_COMP(s) do {                                                       \
    const uint32_t* ah = AH + (s) * G1_STAGE;                                 \
    const uint32_t* al = AL + (s) * G1_STAGE;                                 \
    const uint32_t* bh = BH + (s) * G1_STAGE;                                 \
    const uint32_t* bl = BL + (s) * G1_STAGE;                                 \
    _Pragma("unroll")                                                         \
    for (int ks = 0; ks < 4; ks++) {                                          \
        const int kw = ks * 8;                                                \
        const int ab = (m0 + gr) * G1_S + kw + p;                             \
        uint32_t Ah[4] = { ah[ab], ah[ab + 8 * G1_S], ah[ab + 4], ah[ab + 8 * G1_S + 4] }; \
        uint32_t Alr[4] = { al[ab], al[ab + 8 * G1_S], al[ab + 4], al[ab + 8 * G1_S + 4] }; \
        uint32_t Bh[4][2], Blr[4][2];                                         \
        _Pragma("unroll")                                                     \
        for (int nt = 0; nt < 4; nt++) {                                      \
            const int bb = (n0 + nt * 8 + gr) * G1_S + kw + p;                \
            Bh[nt][0] = bh[bb]; Bh[nt][1] = bh[bb + 4];                       \
            Blr[nt][0] = bl[bb]; Blr[nt][1] = bl[bb + 4];                     \
        }                                                                     \
        _Pragma("unroll")                                                     \
        for (int nt = 0; nt < 4; nt++) mma_bf16(acc[nt], Ah, Bh[nt]);         \
        _Pragma("unroll")                                                     \
        for (int nt = 0; nt < 4; nt++) mma_bf16(acc[nt], Ah, Blr[nt]);        \
        _Pragma("unroll")                                                     \
        for (int nt = 0; nt < 4; nt++) mma_bf16(acc[nt], Alr, Bh[nt]);        \
    }                                                                         \
} while (0)

    G1_LOAD(0, 0);
    __syncthreads();
    for (int c = 0; c < 64; c++) {
        const int s = c & 1;
        if (c < 63) G1_LOAD(s ^ 1, c + 1);
        G1_COMP(s);
        __syncthreads();
    }

    // u -> us (aliases stage buffers; k-loop fully done)
#pragma unroll
    for (int nt = 0; nt < 4; nt++) {
        const int col = n0 + nt * 8 + 2 * p;
        float* u0 = us + (m0 + gr) * 68 + col;
        float* u1 = us + (m0 + gr + 8) * 68 + col;
        u0[0] = acc[nt][0]; u0[1] = acc[nt][1];
        u1[0] = acc[nt][2]; u1[1] = acc[nt][3];
    }
    __syncthreads();

    // v = u @ W1[t]; thread: rows ty+16q (q<4), cols tx*4..+3
    const int tx = tid & 15, ty = tid >> 4;
    u64 vac[4][2];
#pragma unroll
    for (int q = 0; q < 4; q++) { vac[q][0] = 0ull; vac[q][1] = 0ull; }
#pragma unroll 8
    for (int k = 0; k < R_; k++) {
        ulonglong2 w = *(const ulonglong2*)&W1s[k * 64 + tx * 4];
#pragma unroll
        for (int q = 0; q < 4; q++) {
            float a = us[(ty + 16 * q) * 68 + k];
            u64 a2 = pk2(a, a);
            vac[q][0] = ffma2(a2, w.x, vac[q][0]);
            vac[q][1] = ffma2(a2, w.y, vac[q][1]);
        }
    }
#pragma unroll
    for (int q = 0; q < 4; q++) {
        float4 v;
        upk2(vac[q][0], v.x, v.y);
        upk2(vac[q][1], v.z, v.w);
        uint32_t h01, h23, l01, l23;
        split4(v, h01, h23, l01, l23);
        const size_t go = (size_t)(t + 8 * (g * 64 + ty + 16 * q)) * 64 + tx * 4;
        *(uint2*)&g_vhi[go] = make_uint2(h01, h23);
        *(uint2*)&g_vlo[go] = make_uint2(l01, l23);
    }
}

// ---------------------------------------------------------------------------
// k_gemm2: y = v @ out_core^T. CTA tile 128x128, K=64 single shot, 3-term.
// smem: AH[128][36w]@0, AL@18432, BH@36864, BL@55296.  grid (32, 64).
// ---------------------------------------------------------------------------
#define G2_SMEM 73728

__global__ __launch_bounds__(256) void k_gemm2(float* __restrict__ y) {
    extern __shared__ char sm[];
    uint32_t* AH = (uint32_t*)sm;
    uint32_t* AL = (uint32_t*)(sm + 18432);
    uint32_t* BH = (uint32_t*)(sm + 36864);
    uint32_t* BL = (uint32_t*)(sm + 55296);

    const int tid = threadIdx.x, warp = tid >> 5, lane = tid & 31;
    const int gr = lane >> 2, p = lane & 3;
    const int n0b = blockIdx.x * 128, m0b = blockIdx.y * 128;

    {
        const int row = tid >> 1, q = tid & 1;
        const uint4* avh = (const uint4*)(g_vhi + (size_t)(m0b + row) * 64 + q * 32);
        const uint4* avl = (const uint4*)(g_vlo + (size_t)(m0b + row) * 64 + q * 32);
        const uint4* obh = (const uint4*)(g_ochi + (size_t)(n0b + row) * 64 + q * 32);
        const uint4* obl = (const uint4*)(g_oclo + (size_t)(n0b + row) * 64 + q * 32);
        uint32_t* da = AH + row * G1_S + q * 16;
        uint32_t* dal = AL + row * G1_S + q * 16;
        uint32_t* db = BH + row * G1_S + q * 16;
        uint32_t* dbl = BL + row * G1_S + q * 16;
#pragma unroll
        for (int j = 0; j < 4; j++) {
            *(uint4*)(da + j * 4) = avh[j];
            *(uint4*)(dal + j * 4) = avl[j];
            *(uint4*)(db + j * 4) = obh[j];
            *(uint4*)(dbl + j * 4) = obl[j];
        }
    }
    __syncthreads();

    const int m0 = (warp >> 2) * 64, n0 = (warp & 3) * 32;
    float acc[4][4][4];
#pragma unroll
    for (int mt = 0; mt < 4; mt++)
#pragma unroll
        for (int nt = 0; nt < 4; nt++)
            acc[mt][nt][0] = acc[mt][nt][1] = acc[mt][nt][2] = acc[mt][nt][3] = 0.f;

#pragma unroll
    for (int ks = 0; ks < 4; ks++) {
        const int kw = ks * 8;
        uint32_t Ah[4][4], Alr[4][4];
#pragma unroll
        for (int mt = 0; mt < 4; mt++) {
            const int ab = (m0 + mt * 16 + gr) * G1_S + kw + p;
            Ah[mt][0] = AH[ab]; Ah[mt][1] = AH[ab + 8 * G1_S];
            Ah[mt][2] = AH[ab + 4]; Ah[mt][3] = AH[ab + 8 * G1_S + 4];
            Alr[mt][0] = AL[ab]; Alr[mt][1] = AL[ab + 8 * G1_S];
            Alr[mt][2] = AL[ab + 4]; Alr[mt][3] = AL[ab + 8 * G1_S + 4];
        }
        uint32_t Bh[4][2], Blr[4][2];
#pragma unroll
        for (int nt = 0; nt < 4; nt++) {
            const int bb = (n0 + nt * 8 + gr) * G1_S + kw + p;
            Bh[nt][0] = BH[bb]; Bh[nt][1] = BH[bb + 4];
            Blr[nt][0] = BL[bb]; Blr[nt][1] = BL[bb + 4];
        }
#pragma unroll
        for (int mt = 0; mt < 4; mt++)
#pragma unroll
            for (int nt = 0; nt < 4; nt++) mma_bf16(acc[mt][nt], Ah[mt], Bh[nt]);
#pragma unroll
        for (int mt = 0; mt < 4; mt++)
#pragma unroll
            for (int nt = 0; nt < 4; nt++) mma_bf16(acc[mt][nt], Ah[mt], Blr[nt]);
#pragma unroll
        for (int mt = 0; mt < 4; mt++)
#pragma unroll
            for (int nt = 0; nt < 4; nt++) mma_bf16(acc[mt][nt], Alr[mt], Bh[nt]);
    }

#pragma unroll
    for (int mt = 0; mt < 4; mt++) {
#pragma unroll
        for (int nt = 0; nt < 4; nt++) {
            const int row = m0b + m0 + mt * 16 + gr;
            const int col = n0b + n0 + nt * 8 + 2 * p;
            *(float2*)&y[(size_t)row * OUT_ + col] =
                make_float2(acc[mt][nt][0], acc[mt][nt][1]);
            *(float2*)&y[(size_t)(row + 8) * OUT_ + col] =
                make_float2(acc[mt][nt][2], acc[mt][nt][3]);
        }
    }
}

// ---------------------------------------------------------------------------
extern "C" void kernel_launch(void* const* d_in, const int* in_sizes, int n_in,
                              void* d_out, int out_size) {
    const float* x        = (const float*)d_in[0];
    const float* tc       = (const float*)d_in[1];
    const float* task     = (const float*)d_in[2];
    const float* in_core  = (const float*)d_in[3];
    const float* out_core = (const float*)d_in[4];
    float* y = (float*)d_out;

    cudaFuncSetAttribute(k_gemm1, cudaFuncAttributeMaxDynamicSharedMemorySize, G1_SMEM);
    cudaFuncSetAttribute(k_gemm2, cudaFuncAttributeMaxDynamicSharedMemorySize, G2_SMEM);

    k_prep<<<256, 256>>>(task, tc, in_core, out_core);
    k_gemm1<<<128, 256, G1_SMEM>>>(x);
    k_gemm2<<<dim3(OUT_ / 128, BT_ / 128), 256, G2_SMEM>>>(y);
}

// round 5
// speedup vs baseline: 3.1260x; 1.5891x over previous
#include <cuda_runtime.h>
#include <cuda_bf16.h>
#include <cstdint>

#define BT_   8192
#define IN_   4096
#define OUT_  4096
#define R_    64
#define T_    8

// ---------------- device scratch ----------------
__device__ float          g_W1[T_ * R_ * R_];
__device__ __nv_bfloat16  g_Bthi[T_ * R_ * IN_];   // Bt = in_core@W1 : [t][n][k]
__device__ __nv_bfloat16  g_Btlo[T_ * R_ * IN_];
__device__ __nv_bfloat16  g_ochi[OUT_ * R_];       // out_core [n][k]
__device__ __nv_bfloat16  g_oclo[OUT_ * R_];
__device__ float          g_vpart[4][BT_ * R_];    // split-K partials of v
__device__ __nv_bfloat16  g_vhi[BT_ * R_];
__device__ __nv_bfloat16  g_vlo[BT_ * R_];

typedef unsigned long long u64;

// ---------- packed f32x2 ----------
__device__ __forceinline__ u64 pk2(float lo, float hi) {
    u64 r; asm("mov.b64 %0, {%1, %2};" : "=l"(r) : "f"(lo), "f"(hi)); return r;
}
__device__ __forceinline__ void upk2(u64 v, float& lo, float& hi) {
    asm("mov.b64 {%0, %1}, %2;" : "=f"(lo), "=f"(hi) : "l"(v));
}
__device__ __forceinline__ u64 ffma2(u64 a, u64 b, u64 c) {
    u64 d; asm("fma.rn.f32x2 %0, %1, %2, %3;" : "=l"(d) : "l"(a), "l"(b), "l"(c)); return d;
}

// ---------- fp32 -> bf16 hi/lo split ----------
__device__ __forceinline__ void split4(float4 v, uint32_t& h01, uint32_t& h23,
                                       uint32_t& l01, uint32_t& l23) {
    __nv_bfloat162 h0 = __floats2bfloat162_rn(v.x, v.y);
    __nv_bfloat162 h1 = __floats2bfloat162_rn(v.z, v.w);
    float rx = v.x - __bfloat162float(h0.x);
    float ry = v.y - __bfloat162float(h0.y);
    float rz = v.z - __bfloat162float(h1.x);
    float rw = v.w - __bfloat162float(h1.y);
    __nv_bfloat162 l0 = __floats2bfloat162_rn(rx, ry);
    __nv_bfloat162 l1 = __floats2bfloat162_rn(rz, rw);
    h01 = *(uint32_t*)&h0; h23 = *(uint32_t*)&h1;
    l01 = *(uint32_t*)&l0; l23 = *(uint32_t*)&l1;
}

// ---------- tensor-core primitives (base-ISA, sm_103-safe) ----------
__device__ __forceinline__ void mma16816(float* c, uint32_t a0, uint32_t a1,
                                         uint32_t a2, uint32_t a3,
                                         uint32_t b0, uint32_t b1) {
    asm volatile(
        "mma.sync.aligned.m16n8k16.row.col.f32.bf16.bf16.f32 "
        "{%0,%1,%2,%3}, {%4,%5,%6,%7}, {%8,%9}, {%0,%1,%2,%3};"
        : "+f"(c[0]), "+f"(c[1]), "+f"(c[2]), "+f"(c[3])
        : "r"(a0), "r"(a1), "r"(a2), "r"(a3), "r"(b0), "r"(b1));
}
__device__ __forceinline__ void ldsm4(uint32_t* r, uint32_t saddr) {
    asm volatile("ldmatrix.sync.aligned.m8n8.x4.shared.b16 {%0,%1,%2,%3}, [%4];"
                 : "=r"(r[0]), "=r"(r[1]), "=r"(r[2]), "=r"(r[3]) : "r"(saddr));
}
__device__ __forceinline__ void cpa16(uint32_t dst, const void* src) {
    asm volatile("cp.async.cg.shared.global [%0], [%1], 16;" :: "r"(dst), "l"(src));
}
#define CP_COMMIT() asm volatile("cp.async.commit_group;" ::: "memory")
#define CP_WAIT0()  asm volatile("cp.async.wait_group 0;" ::: "memory")

__device__ __forceinline__ uint32_t smem_u32(const void* p) {
    uint32_t a;
    asm("{ .reg .u64 t; cvta.to.shared.u64 t, %1; cvt.u32.u64 %0, t; }" : "=r"(a) : "l"(p));
    return a;
}

// row stride in all smem tile matrices: 144 bytes (36 words) -> LDSM conflict-free
#define RSTR 144

// ---------------------------------------------------------------------------
// k_pre1: out_core hi/lo split (bx<64) + W1 (bx in [64,192)).
// ---------------------------------------------------------------------------
__global__ __launch_bounds__(256) void k_pre1(const float* __restrict__ task,
                                              const float* __restrict__ tc,
                                              const float* __restrict__ out_core) {
    const int bx = blockIdx.x, tid = threadIdx.x;
    if (bx < 64) {
        const size_t base = (size_t)bx * 4096 + (size_t)tid * 16;
#pragma unroll
        for (int j = 0; j < 16; j += 4) {
            float4 v = *(const float4*)&out_core[base + j];
            uint32_t h01, h23, l01, l23;
            split4(v, h01, h23, l01, l23);
            *(uint32_t*)&g_ochi[base + j]     = h01;
            *(uint32_t*)&g_ochi[base + j + 2] = h23;
            *(uint32_t*)&g_oclo[base + j]     = l01;
            *(uint32_t*)&g_oclo[base + j + 2] = l23;
        }
    } else {
        const int idx = (bx - 64) * 256 + tid;
        const int t = idx >> 12, kl = idx & 4095;
        float a0 = 0, a1 = 0, a2 = 0, a3 = 0;
#pragma unroll
        for (int j = 0; j < 64; j += 4) {
            a0 += task[t * 64 + j + 0] * tc[(size_t)(j + 0) * 4096 + kl];
            a1 += task[t * 64 + j + 1] * tc[(size_t)(j + 1) * 4096 + kl];
            a2 += task[t * 64 + j + 2] * tc[(size_t)(j + 2) * 4096 + kl];
            a3 += task[t * 64 + j + 3] * tc[(size_t)(j + 3) * 4096 + kl];
        }
        g_W1[idx] = (a0 + a1) + (a2 + a3);
    }
}

// ---------------------------------------------------------------------------
// k_bt: Bt[t][k][n] = sum_j in_core[k][j] * W1[t][j][n], split to bf16 hi/lo,
// stored transposed as [t][n][k].  grid 128: t = bx>>4, kc = (bx&15)*256.
// ---------------------------------------------------------------------------
__global__ __launch_bounds__(256) void k_bt(const float* __restrict__ in_core) {
    __shared__ float W1s[4096];
    const int bx = blockIdx.x, tid = threadIdx.x;
    const int t = bx >> 4;
    const int row = (bx & 15) * 256 + tid;      // k index
    {
        const float4* src = (const float4*)(g_W1 + t * 4096);
        float4* dst = (float4*)W1s;
#pragma unroll
        for (int i = 0; i < 4; i++) dst[tid + i * 256] = src[tid + i * 256];
    }
    __syncthreads();

    u64 acc[32];
#pragma unroll
    for (int i = 0; i < 32; i++) acc[i] = 0ull;

    const float* icr = in_core + (size_t)row * 64;
#pragma unroll
    for (int jc = 0; jc < 4; jc++) {
        float4 a4[4];
#pragma unroll
        for (int q = 0; q < 4; q++) a4[q] = *(const float4*)(icr + jc * 16 + q * 4);
#pragma unroll
        for (int jj = 0; jj < 16; jj++) {
            const int j = jc * 16 + jj;
            float a = ((const float*)a4)[jj];
            u64 a2 = pk2(a, a);
#pragma unroll
            for (int i2 = 0; i2 < 16; i2++) {
                ulonglong2 w = *(const ulonglong2*)&W1s[j * 64 + i2 * 4];
                acc[2 * i2]     = ffma2(a2, w.x, acc[2 * i2]);
                acc[2 * i2 + 1] = ffma2(a2, w.y, acc[2 * i2 + 1]);
            }
        }
    }
    // split + transposed store: Bt[t][n][row]
#pragma unroll
    for (int i = 0; i < 32; i++) {
        float v0, v1;
        upk2(acc[i], v0, v1);
        __nv_bfloat16 h0 = __float2bfloat16(v0);
        __nv_bfloat16 l0 = __float2bfloat16(v0 - __bfloat162float(h0));
        __nv_bfloat16 h1 = __float2bfloat16(v1);
        __nv_bfloat16 l1 = __float2bfloat16(v1 - __bfloat162float(h1));
        const size_t b0 = ((size_t)t * 64 + 2 * i) * IN_ + row;
        const size_t b1 = ((size_t)t * 64 + 2 * i + 1) * IN_ + row;
        g_Bthi[b0] = h0; g_Btlo[b0] = l0;
        g_Bthi[b1] = h1; g_Btlo[b1] = l1;
    }
}

// ---------------------------------------------------------------------------
// k_gemm1: v_partial = x @ Bt[t]  (tile 64m x 64n, K-slice 1024 = 16 chunks
// of 64). 512 CTAs: mtile = bx>>2 (t = mtile&7, g = mtile>>3), kslice = bx&3.
// bf16 hi/lo 3-term mma.sync with ldmatrix; B via cp.async; x split inline.
// smem/stage 36864B: AH@0 AL@9216 BH@18432 BL@27648;  2 stages = 73728B.
// ---------------------------------------------------------------------------
#define G1_SMEM 73728

__global__ __launch_bounds__(256, 2) void k_gemm1(const float* __restrict__ x) {
    extern __shared__ char sm[];
    const uint32_t sb = smem_u32(sm);
    const int tid = threadIdx.x, warp = tid >> 5, lane = tid & 31;
    const int gr = lane >> 2, p = lane & 3;
    const int bx = blockIdx.x;
    const int mtile = bx >> 2, ksl = bx & 3;
    const int t = mtile & 7, g = mtile >> 3;
    const int koff = ksl * 1024;

    // x loader mapping: 4 threads per row
    const int lrow = tid >> 2, lq = tid & 3;
    const float* xrp = x + (size_t)(t + 8 * (g * 64 + lrow)) * IN_ + koff;
    char* xh_base = sm + lrow * RSTR + lq * 8;   // + seg*32 ; AL at +9216

    // B cp.async mapping
    const int bn = tid >> 2, bj = tid & 3;
    const __nv_bfloat16* bth = g_Bthi + ((size_t)t * 64 + bn) * IN_ + koff;
    const __nv_bfloat16* btl = g_Btlo + ((size_t)t * 64 + bn) * IN_ + koff;
    const uint32_t dB = sb + 18432 + bn * RSTR;

    // ldmatrix lane roles
    const int m0 = (warp >> 1) * 16, n0 = (warp & 1) * 32;
    const int lr = (lane & 7) + ((lane >> 3) & 1) * 8;
    const int lk = (lane >> 4) * 16;
    const uint32_t offA = (uint32_t)((m0 + lr) * RSTR + lk);
    const uint32_t offB = (uint32_t)((n0 + lr) * RSTR + lk);

    float acc[4][4];
#pragma unroll
    for (int i = 0; i < 4; i++) acc[i][0] = acc[i][1] = acc[i][2] = acc[i][3] = 0.f;

#define G1_XLOAD(st_, c_) do {                                                \
    char* ah = sm + (st_) * 36864 + lrow * RSTR + lq * 8;                     \
    const float* srcx = xrp + (c_) * 64;                                      \
    _Pragma("unroll")                                                         \
    for (int seg = 0; seg < 4; seg++) {                                       \
        float4 v = *(const float4*)(srcx + seg * 16 + lq * 4);                \
        uint32_t h01, h23, l01, l23;                                          \
        split4(v, h01, h23, l01, l23);                                        \
        *(uint2*)(ah + seg * 32)        = make_uint2(h01, h23);               \
        *(uint2*)(ah + 9216 + seg * 32) = make_uint2(l01, l23);               \
    }                                                                         \
} while (0)

#define G1_BLOAD(st_, c_) do {                                                \
    const uint32_t d = dB + (st_) * 36864;                                    \
    cpa16(d + bj * 16,        bth + (c_) * 64 + bj * 8);                      \
    cpa16(d + (bj + 4) * 16,  bth + (c_) * 64 + (bj + 4) * 8);                \
    cpa16(d + 9216 + bj * 16,       btl + (c_) * 64 + bj * 8);                \
    cpa16(d + 9216 + (bj + 4) * 16, btl + (c_) * 64 + (bj + 4) * 8);          \
} while (0)

    // prologue: chunk 0 -> stage 0
    G1_BLOAD(0, 0);
    CP_COMMIT();
    G1_XLOAD(0, 0);

    for (int c = 0; c < 16; c++) {
        const int s = c & 1;
        CP_WAIT0();
        __syncthreads();
        if (c < 15) {
            G1_BLOAD(s ^ 1, c + 1);
            CP_COMMIT();
            G1_XLOAD(s ^ 1, c + 1);
        }
        // compute chunk c from stage s
        const uint32_t st = sb + s * 36864;
#pragma unroll
        for (int ks = 0; ks < 4; ks++) {
            const uint32_t ka = ks * 32;
            uint32_t Ah[4], Al[4], B0[4], B1[4], L0[4], L1[4];
            ldsm4(Ah, st + offA + ka);
            ldsm4(B0, st + 18432 + offB + ka);
            ldsm4(B1, st + 18432 + 16 * RSTR + offB + ka);
            ldsm4(Al, st + 9216 + offA + ka);
            ldsm4(L0, st + 27648 + offB + ka);
            ldsm4(L1, st + 27648 + 16 * RSTR + offB + ka);
            // hi*hi
            mma16816(acc[0], Ah[0], Ah[1], Ah[2], Ah[3], B0[0], B0[2]);
            mma16816(acc[1], Ah[0], Ah[1], Ah[2], Ah[3], B0[1], B0[3]);
            mma16816(acc[2], Ah[0], Ah[1], Ah[2], Ah[3], B1[0], B1[2]);
            mma16816(acc[3], Ah[0], Ah[1], Ah[2], Ah[3], B1[1], B1[3]);
            // lo*hi
            mma16816(acc[0], Al[0], Al[1], Al[2], Al[3], B0[0], B0[2]);
            mma16816(acc[1], Al[0], Al[1], Al[2], Al[3], B0[1], B0[3]);
            mma16816(acc[2], Al[0], Al[1], Al[2], Al[3], B1[0], B1[2]);
            mma16816(acc[3], Al[0], Al[1], Al[2], Al[3], B1[1], B1[3]);
            // hi*lo
            mma16816(acc[0], Ah[0], Ah[1], Ah[2], Ah[3], L0[0], L0[2]);
            mma16816(acc[1], Ah[0], Ah[1], Ah[2], Ah[3], L0[1], L0[3]);
            mma16816(acc[2], Ah[0], Ah[1], Ah[2], Ah[3], L1[0], L1[2]);
            mma16816(acc[3], Ah[0], Ah[1], Ah[2], Ah[3], L1[1], L1[3]);
        }
    }

    // store partials (deterministic plain stores)
    float* vp = g_vpart[ksl];
    const size_t r0 = (size_t)(t + 8 * (g * 64 + m0 + gr));
    const size_t r1 = r0 + 64;   // row + 8 in tile = +64 global
#pragma unroll
    for (int nt = 0; nt < 4; nt++) {
        const int col = n0 + nt * 8 + 2 * p;
        *(float2*)&vp[r0 * 64 + col] = make_float2(acc[nt][0], acc[nt][1]);
        *(float2*)&vp[r1 * 64 + col] = make_float2(acc[nt][2], acc[nt][3]);
    }
}

// ---------------------------------------------------------------------------
// k_vred: v = sum of 4 partials, split to bf16 hi/lo.  512 blocks x 256 thr.
// ---------------------------------------------------------------------------
__global__ __launch_bounds__(256) void k_vred() {
    const int idx = blockIdx.x * 256 + threadIdx.x;   // float4 index
    const float4* p0 = (const float4*)g_vpart[0];
    const float4* p1 = (const float4*)g_vpart[1];
    const float4* p2 = (const float4*)g_vpart[2];
    const float4* p3 = (const float4*)g_vpart[3];
    float4 a = p0[idx], b = p1[idx], c = p2[idx], d = p3[idx];
    float4 s = make_float4(((a.x + b.x) + c.x) + d.x, ((a.y + b.y) + c.y) + d.y,
                           ((a.z + b.z) + c.z) + d.z, ((a.w + b.w) + c.w) + d.w);
    uint32_t h01, h23, l01, l23;
    split4(s, h01, h23, l01, l23);
    *(uint2*)&g_vhi[(size_t)idx * 4] = make_uint2(h01, h23);
    *(uint2*)&g_vlo[(size_t)idx * 4] = make_uint2(l01, l23);
}

// ---------------------------------------------------------------------------
// k_gemm2: y = v @ out_core^T. Tile 128x128, K=64 one shot, warp tile 64x32.
// smem: AH@0 AL@18432 BH@36864 BL@55296 (128 rows x 144B each) = 73728B.
// ---------------------------------------------------------------------------
#define G2_SMEM 73728

__global__ __launch_bounds__(256) void k_gemm2(float* __restrict__ y) {
    extern __shared__ char sm[];
    const uint32_t sb = smem_u32(sm);
    const int tid = threadIdx.x, warp = tid >> 5, lane = tid & 31;
    const int gr = lane >> 2, p = lane & 3;
    const int n0b = blockIdx.x * 128, m0b = blockIdx.y * 128;

    {   // cp.async all 4 tiles
        const int row = tid >> 1, q = (tid & 1) * 4;
        const uint32_t drow = sb + row * RSTR;
        const __nv_bfloat16* sa = g_vhi  + (size_t)(m0b + row) * 64;
        const __nv_bfloat16* sal = g_vlo + (size_t)(m0b + row) * 64;
        const __nv_bfloat16* sbh = g_ochi + (size_t)(n0b + row) * 64;
        const __nv_bfloat16* sbl = g_oclo + (size_t)(n0b + row) * 64;
#pragma unroll
        for (int j = 0; j < 4; j++) {
            cpa16(drow + (q + j) * 16,         sa  + (q + j) * 8);
            cpa16(drow + 18432 + (q + j) * 16, sal + (q + j) * 8);
            cpa16(drow + 36864 + (q + j) * 16, sbh + (q + j) * 8);
            cpa16(drow + 55296 + (q + j) * 16, sbl + (q + j) * 8);
        }
    }
    CP_COMMIT();
    CP_WAIT0();
    __syncthreads();

    const int m0 = (warp >> 2) * 64, n0 = (warp & 3) * 32;
    const int lr = (lane & 7) + ((lane >> 3) & 1) * 8;
    const int lk = (lane >> 4) * 16;
    const uint32_t offA = (uint32_t)((m0 + lr) * RSTR + lk);
    const uint32_t offB = (uint32_t)((n0 + lr) * RSTR + lk);

    float acc[4][4][4];
#pragma unroll
    for (int mt = 0; mt < 4; mt++)
#pragma unroll
        for (int nt = 0; nt < 4; nt++)
            acc[mt][nt][0] = acc[mt][nt][1] = acc[mt][nt][2] = acc[mt][nt][3] = 0.f;

#pragma unroll
    for (int ks = 0; ks < 4; ks++) {
        const uint32_t ka = ks * 32;
        uint32_t Ah[4][4], Al[4][4], B0[4], B1[4], L0[4], L1[4];
#pragma unroll
        for (int mt = 0; mt < 4; mt++)
            ldsm4(Ah[mt], sb + offA + mt * 16 * RSTR + ka);
        ldsm4(B0, sb + 36864 + offB + ka);
        ldsm4(B1, sb + 36864 + 16 * RSTR + offB + ka);
        // hi*hi
#pragma unroll
        for (int mt = 0; mt < 4; mt++) {
            mma16816(acc[mt][0], Ah[mt][0], Ah[mt][1], Ah[mt][2], Ah[mt][3], B0[0], B0[2]);
            mma16816(acc[mt][1], Ah[mt][0], Ah[mt][1], Ah[mt][2], Ah[mt][3], B0[1], B0[3]);
            mma16816(acc[mt][2], Ah[mt][0], Ah[mt][1], Ah[mt][2], Ah[mt][3], B1[0], B1[2]);
            mma16816(acc[mt][3], Ah[mt][0], Ah[mt][1], Ah[mt][2], Ah[mt][3], B1[1], B1[3]);
        }
        // hi*lo
        ldsm4(L0, sb + 55296 + offB + ka);
        ldsm4(L1, sb + 55296 + 16 * RSTR + offB + ka);
#pragma unroll
        for (int mt = 0; mt < 4; mt++) {
            mma16816(acc[mt][0], Ah[mt][0], Ah[mt][1], Ah[mt][2], Ah[mt][3], L0[0], L0[2]);
            mma16816(acc[mt][1], Ah[mt][0], Ah[mt][1], Ah[mt][2], Ah[mt][3], L0[1], L0[3]);
            mma16816(acc[mt][2], Ah[mt][0], Ah[mt][1], Ah[mt][2], Ah[mt][3], L1[0], L1[2]);
            mma16816(acc[mt][3], Ah[mt][0], Ah[mt][1], Ah[mt][2], Ah[mt][3], L1[1], L1[3]);
        }
        // lo*hi
#pragma unroll
        for (int mt = 0; mt < 4; mt++)
            ldsm4(Al[mt], sb + 18432 + offA + mt * 16 * RSTR + ka);
#pragma unroll
        for (int mt = 0; mt < 4; mt++) {
            mma16816(acc[mt][0], Al[mt][0], Al[mt][1], Al[mt][2], Al[mt][3], B0[0], B0[2]);
            mma16816(acc[mt][1], Al[mt][0], Al[mt][1], Al[mt][2], Al[mt][3], B0[1], B0[3]);
            mma16816(acc[mt][2], Al[mt][0], Al[mt][1], Al[mt][2], Al[mt][3], B1[0], B1[2]);
            mma16816(acc[mt][3], Al[mt][0], Al[mt][1], Al[mt][2], Al[mt][3], B1[1], B1[3]);
        }
    }

#pragma unroll
    for (int mt = 0; mt < 4; mt++) {
#pragma unroll
        for (int nt = 0; nt < 4; nt++) {
            const int row = m0b + m0 + mt * 16 + gr;
            const int col = n0b + n0 + nt * 8 + 2 * p;
            *(float2*)&y[(size_t)row * OUT_ + col] =
                make_float2(acc[mt][nt][0], acc[mt][nt][1]);
            *(float2*)&y[(size_t)(row + 8) * OUT_ + col] =
                make_float2(acc[mt][nt][2], acc[mt][nt][3]);
        }
    }
}

// ---------------------------------------------------------------------------
extern "C" void kernel_launch(void* const* d_in, const int* in_sizes, int n_in,
                              void* d_out, int out_size) {
    const float* x        = (const float*)d_in[0];
    const float* tc       = (const float*)d_in[1];
    const float* task     = (const float*)d_in[2];
    const float* in_core  = (const float*)d_in[3];
    const float* out_core = (const float*)d_in[4];
    float* y = (float*)d_out;

    cudaFuncSetAttribute(k_gemm1, cudaFuncAttributeMaxDynamicSharedMemorySize, G1_SMEM);
    cudaFuncSetAttribute(k_gemm2, cudaFuncAttributeMaxDynamicSharedMemorySize, G2_SMEM);

    k_pre1<<<192, 256>>>(task, tc, out_core);
    k_bt<<<128, 256>>>(in_core);
    k_gemm1<<<512, 256, G1_SMEM>>>(x);
    k_vred<<<512, 256>>>();
    k_gemm2<<<dim3(OUT_ / 128, BT_ / 128), 256, G2_SMEM>>>(y);
}

// round 6
// speedup vs baseline: 3.2502x; 1.0397x over previous
#include <cuda_runtime.h>
#include <cuda_bf16.h>
#include <cstdint>

#define BT_   8192
#define IN_   4096
#define OUT_  4096
#define R_    64
#define T_    8

// ---------------- device scratch ----------------
__device__ float          g_W1[T_ * R_ * R_];
__device__ __nv_bfloat16  g_Bthi[T_ * R_ * IN_];   // Bt = in_core@W1 : [t][n][k]
__device__ __nv_bfloat16  g_Btlo[T_ * R_ * IN_];
__device__ __nv_bfloat16  g_ochi[OUT_ * R_];       // out_core [n][k]
__device__ __nv_bfloat16  g_oclo[OUT_ * R_];
__device__ float          g_vpart[2][BT_ * R_];    // split-K partials of v
__device__ __nv_bfloat16  g_vhi[BT_ * R_];
__device__ __nv_bfloat16  g_vlo[BT_ * R_];

typedef unsigned long long u64;

// ---------- packed f32x2 ----------
__device__ __forceinline__ u64 pk2(float lo, float hi) {
    u64 r; asm("mov.b64 %0, {%1, %2};" : "=l"(r) : "f"(lo), "f"(hi)); return r;
}
__device__ __forceinline__ void upk2(u64 v, float& lo, float& hi) {
    asm("mov.b64 {%0, %1}, %2;" : "=f"(lo), "=f"(hi) : "l"(v));
}
__device__ __forceinline__ u64 ffma2(u64 a, u64 b, u64 c) {
    u64 d; asm("fma.rn.f32x2 %0, %1, %2, %3;" : "=l"(d) : "l"(a), "l"(b), "l"(c)); return d;
}

// ---------- fp32 -> bf16 hi/lo split ----------
__device__ __forceinline__ void split4(float4 v, uint32_t& h01, uint32_t& h23,
                                       uint32_t& l01, uint32_t& l23) {
    __nv_bfloat162 h0 = __floats2bfloat162_rn(v.x, v.y);
    __nv_bfloat162 h1 = __floats2bfloat162_rn(v.z, v.w);
    float rx = v.x - __bfloat162float(h0.x);
    float ry = v.y - __bfloat162float(h0.y);
    float rz = v.z - __bfloat162float(h1.x);
    float rw = v.w - __bfloat162float(h1.y);
    __nv_bfloat162 l0 = __floats2bfloat162_rn(rx, ry);
    __nv_bfloat162 l1 = __floats2bfloat162_rn(rz, rw);
    h01 = *(uint32_t*)&h0; h23 = *(uint32_t*)&h1;
    l01 = *(uint32_t*)&l0; l23 = *(uint32_t*)&l1;
}

// ---------- tensor-core primitives (base-ISA, sm_103-safe) ----------
__device__ __forceinline__ void mma16816(float* c, uint32_t a0, uint32_t a1,
                                         uint32_t a2, uint32_t a3,
                                         uint32_t b0, uint32_t b1) {
    asm volatile(
        "mma.sync.aligned.m16n8k16.row.col.f32.bf16.bf16.f32 "
        "{%0,%1,%2,%3}, {%4,%5,%6,%7}, {%8,%9}, {%0,%1,%2,%3};"
        : "+f"(c[0]), "+f"(c[1]), "+f"(c[2]), "+f"(c[3])
        : "r"(a0), "r"(a1), "r"(a2), "r"(a3), "r"(b0), "r"(b1));
}
__device__ __forceinline__ void ldsm4(uint32_t* r, uint32_t saddr) {
    asm volatile("ldmatrix.sync.aligned.m8n8.x4.shared.b16 {%0,%1,%2,%3}, [%4];"
                 : "=r"(r[0]), "=r"(r[1]), "=r"(r[2]), "=r"(r[3]) : "r"(saddr));
}
__device__ __forceinline__ void cpa16(uint32_t dst, const void* src) {
    asm volatile("cp.async.cg.shared.global [%0], [%1], 16;" :: "r"(dst), "l"(src));
}
#define CP_COMMIT() asm volatile("cp.async.commit_group;" ::: "memory")
#define CP_WAIT0()  asm volatile("cp.async.wait_group 0;" ::: "memory")

__device__ __forceinline__ uint32_t smem_u32(const void* p) {
    uint32_t a;
    asm("{ .reg .u64 t; cvta.to.shared.u64 t, %1; cvt.u32.u64 %0, t; }" : "=r"(a) : "l"(p));
    return a;
}

// row stride in all smem tile matrices: 144 bytes (36 words) -> LDSM conflict-free
#define RSTR 144

// ---------------------------------------------------------------------------
// k_pre1: out_core hi/lo split (bx<64) + W1 (bx in [64,192)).
// ---------------------------------------------------------------------------
__global__ __launch_bounds__(256) void k_pre1(const float* __restrict__ task,
                                              const float* __restrict__ tc,
                                              const float* __restrict__ out_core) {
    const int bx = blockIdx.x, tid = threadIdx.x;
    if (bx < 64) {
        const size_t base = (size_t)bx * 4096 + (size_t)tid * 16;
#pragma unroll
        for (int j = 0; j < 16; j += 4) {
            float4 v = *(const float4*)&out_core[base + j];
            uint32_t h01, h23, l01, l23;
            split4(v, h01, h23, l01, l23);
            *(uint32_t*)&g_ochi[base + j]     = h01;
            *(uint32_t*)&g_ochi[base + j + 2] = h23;
            *(uint32_t*)&g_oclo[base + j]     = l01;
            *(uint32_t*)&g_oclo[base + j + 2] = l23;
        }
    } else {
        const int idx = (bx - 64) * 256 + tid;
        const int t = idx >> 12, kl = idx & 4095;
        float a0 = 0, a1 = 0, a2 = 0, a3 = 0;
#pragma unroll
        for (int j = 0; j < 64; j += 4) {
            a0 += task[t * 64 + j + 0] * tc[(size_t)(j + 0) * 4096 + kl];
            a1 += task[t * 64 + j + 1] * tc[(size_t)(j + 1) * 4096 + kl];
            a2 += task[t * 64 + j + 2] * tc[(size_t)(j + 2) * 4096 + kl];
            a3 += task[t * 64 + j + 3] * tc[(size_t)(j + 3) * 4096 + kl];
        }
        g_W1[idx] = (a0 + a1) + (a2 + a3);
    }
}

// ---------------------------------------------------------------------------
// k_bt: Bt[t][k][n] = sum_j in_core[k][j] * W1[t][j][n], split to bf16 hi/lo,
// stored transposed as [t][n][k].  grid 128: t = bx>>4, kc = (bx&15)*256.
// ---------------------------------------------------------------------------
__global__ __launch_bounds__(256) void k_bt(const float* __restrict__ in_core) {
    __shared__ float W1s[4096];
    const int bx = blockIdx.x, tid = threadIdx.x;
    const int t = bx >> 4;
    const int row = (bx & 15) * 256 + tid;      // k index
    {
        const float4* src = (const float4*)(g_W1 + t * 4096);
        float4* dst = (float4*)W1s;
#pragma unroll
        for (int i = 0; i < 4; i++) dst[tid + i * 256] = src[tid + i * 256];
    }
    __syncthreads();

    u64 acc[32];
#pragma unroll
    for (int i = 0; i < 32; i++) acc[i] = 0ull;

    const float* icr = in_core + (size_t)row * 64;
#pragma unroll
    for (int jc = 0; jc < 4; jc++) {
        float4 a4[4];
#pragma unroll
        for (int q = 0; q < 4; q++) a4[q] = *(const float4*)(icr + jc * 16 + q * 4);
#pragma unroll
        for (int jj = 0; jj < 16; jj++) {
            const int j = jc * 16 + jj;
            float a = ((const float*)a4)[jj];
            u64 a2 = pk2(a, a);
#pragma unroll
            for (int i2 = 0; i2 < 16; i2++) {
                ulonglong2 w = *(const ulonglong2*)&W1s[j * 64 + i2 * 4];
                acc[2 * i2]     = ffma2(a2, w.x, acc[2 * i2]);
                acc[2 * i2 + 1] = ffma2(a2, w.y, acc[2 * i2 + 1]);
            }
        }
    }
    // split + transposed store: Bt[t][n][row]
#pragma unroll
    for (int i = 0; i < 32; i++) {
        float v0, v1;
        upk2(acc[i], v0, v1);
        __nv_bfloat16 h0 = __float2bfloat16(v0);
        __nv_bfloat16 l0 = __float2bfloat16(v0 - __bfloat162float(h0));
        __nv_bfloat16 h1 = __float2bfloat16(v1);
        __nv_bfloat16 l1 = __float2bfloat16(v1 - __bfloat162float(h1));
        const size_t b0 = ((size_t)t * 64 + 2 * i) * IN_ + row;
        const size_t b1 = ((size_t)t * 64 + 2 * i + 1) * IN_ + row;
        g_Bthi[b0] = h0; g_Btlo[b0] = l0;
        g_Bthi[b1] = h1; g_Btlo[b1] = l1;
    }
}

// ---------------------------------------------------------------------------
// k_gemm1: v_partial = x @ Bt[t]  (tile 64m x 64n, K-slice 2048 = 32 chunks
// of 64). 256 CTAs: mtile = bx>>1 (t = mtile&7, g = mtile>>3), kslice = bx&1.
// Pipelined: LDG x(c+1) -> regs BEFORE compute(c); split+STS AFTER compute(c).
// smem/stage 36864B: AH@0 AL@9216 BH@18432 BL@27648;  2 stages = 73728B.
// ---------------------------------------------------------------------------
#define G1_SMEM 73728

__global__ __launch_bounds__(256, 2) void k_gemm1(const float* __restrict__ x) {
    extern __shared__ char sm[];
    const uint32_t sb = smem_u32(sm);
    const int tid = threadIdx.x, warp = tid >> 5, lane = tid & 31;
    const int gr = lane >> 2, p = lane & 3;
    const int bx = blockIdx.x;
    const int mtile = bx >> 1, ksl = bx & 1;
    const int t = mtile & 7, g = mtile >> 3;
    const int koff = ksl * 2048;

    // x loader mapping: 4 threads per row
    const int lrow = tid >> 2, lq = tid & 3;
    const float* xrp = x + (size_t)(t + 8 * (g * 64 + lrow)) * IN_ + koff;

    // B cp.async mapping
    const int bn = tid >> 2, bj = tid & 3;
    const __nv_bfloat16* bth = g_Bthi + ((size_t)t * 64 + bn) * IN_ + koff;
    const __nv_bfloat16* btl = g_Btlo + ((size_t)t * 64 + bn) * IN_ + koff;
    const uint32_t dB = sb + 18432 + bn * RSTR;

    // ldmatrix lane roles
    const int m0 = (warp >> 1) * 16, n0 = (warp & 1) * 32;
    const int lr = (lane & 7) + ((lane >> 3) & 1) * 8;
    const int lk = (lane >> 4) * 16;
    const uint32_t offA = (uint32_t)((m0 + lr) * RSTR + lk);
    const uint32_t offB = (uint32_t)((n0 + lr) * RSTR + lk);

    float acc[4][4];
#pragma unroll
    for (int i = 0; i < 4; i++) acc[i][0] = acc[i][1] = acc[i][2] = acc[i][3] = 0.f;

    float4 xv[4];

#define G1_BLOAD(st_, c_) do {                                                \
    const uint32_t d = dB + (st_) * 36864;                                    \
    cpa16(d + bj * 16,        bth + (c_) * 64 + bj * 8);                      \
    cpa16(d + (bj + 4) * 16,  bth + (c_) * 64 + (bj + 4) * 8);                \
    cpa16(d + 9216 + bj * 16,       btl + (c_) * 64 + bj * 8);                \
    cpa16(d + 9216 + (bj + 4) * 16, btl + (c_) * 64 + (bj + 4) * 8);          \
} while (0)

#define G1_XLDG(c_) do {                                                      \
    const float* srcx = xrp + (c_) * 64;                                      \
    _Pragma("unroll")                                                         \
    for (int seg = 0; seg < 4; seg++)                                         \
        xv[seg] = *(const float4*)(srcx + seg * 16 + lq * 4);                 \
} while (0)

#define G1_XSTS(st_) do {                                                     \
    char* ah = sm + (st_) * 36864 + lrow * RSTR + lq * 8;                     \
    _Pragma("unroll")                                                         \
    for (int seg = 0; seg < 4; seg++) {                                       \
        uint32_t h01, h23, l01, l23;                                          \
        split4(xv[seg], h01, h23, l01, l23);                                  \
        *(uint2*)(ah + seg * 32)        = make_uint2(h01, h23);               \
        *(uint2*)(ah + 9216 + seg * 32) = make_uint2(l01, l23);               \
    }                                                                         \
} while (0)

    // prologue: chunk 0 -> stage 0
    G1_BLOAD(0, 0);
    CP_COMMIT();
    G1_XLDG(0);
    G1_XSTS(0);

    for (int c = 0; c < 32; c++) {
        const int s = c & 1;
        CP_WAIT0();
        __syncthreads();
        if (c < 31) {
            G1_BLOAD(s ^ 1, c + 1);
            CP_COMMIT();
            G1_XLDG(c + 1);          // LDG in flight during compute below
        }
        // compute chunk c from stage s
        const uint32_t st = sb + s * 36864;
#pragma unroll
        for (int ks = 0; ks < 4; ks++) {
            const uint32_t ka = ks * 32;
            uint32_t Ah[4], Al[4], B0[4], B1[4], L0[4], L1[4];
            ldsm4(Ah, st + offA + ka);
            ldsm4(B0, st + 18432 + offB + ka);
            ldsm4(B1, st + 18432 + 16 * RSTR + offB + ka);
            ldsm4(Al, st + 9216 + offA + ka);
            ldsm4(L0, st + 27648 + offB + ka);
            ldsm4(L1, st + 27648 + 16 * RSTR + offB + ka);
            // hi*hi
            mma16816(acc[0], Ah[0], Ah[1], Ah[2], Ah[3], B0[0], B0[2]);
            mma16816(acc[1], Ah[0], Ah[1], Ah[2], Ah[3], B0[1], B0[3]);
            mma16816(acc[2], Ah[0], Ah[1], Ah[2], Ah[3], B1[0], B1[2]);
            mma16816(acc[3], Ah[0], Ah[1], Ah[2], Ah[3], B1[1], B1[3]);
            // lo*hi
            mma16816(acc[0], Al[0], Al[1], Al[2], Al[3], B0[0], B0[2]);
            mma16816(acc[1], Al[0], Al[1], Al[2], Al[3], B0[1], B0[3]);
            mma16816(acc[2], Al[0], Al[1], Al[2], Al[3], B1[0], B1[2]);
            mma16816(acc[3], Al[0], Al[1], Al[2], Al[3], B1[1], B1[3]);
            // hi*lo
            mma16816(acc[0], Ah[0], Ah[1], Ah[2], Ah[3], L0[0], L0[2]);
            mma16816(acc[1], Ah[0], Ah[1], Ah[2], Ah[3], L0[1], L0[3]);
            mma16816(acc[2], Ah[0], Ah[1], Ah[2], Ah[3], L1[0], L1[2]);
            mma16816(acc[3], Ah[0], Ah[1], Ah[2], Ah[3], L1[1], L1[3]);
        }
        if (c < 31) G1_XSTS(s ^ 1);   // split + store AFTER compute (LDG hidden)
    }

    // store partials (deterministic plain stores)
    float* vp = g_vpart[ksl];
    const size_t r0 = (size_t)(t + 8 * (g * 64 + m0 + gr));
    const size_t r1 = r0 + 64;   // row + 8 in tile = +64 global
#pragma unroll
    for (int nt = 0; nt < 4; nt++) {
        const int col = n0 + nt * 8 + 2 * p;
        *(float2*)&vp[r0 * 64 + col] = make_float2(acc[nt][0], acc[nt][1]);
        *(float2*)&vp[r1 * 64 + col] = make_float2(acc[nt][2], acc[nt][3]);
    }
}

// ---------------------------------------------------------------------------
// k_vred: v = sum of 2 partials, split to bf16 hi/lo.  512 blocks x 256 thr.
// ---------------------------------------------------------------------------
__global__ __launch_bounds__(256) void k_vred() {
    const int idx = blockIdx.x * 256 + threadIdx.x;   // float4 index
    const float4* p0 = (const float4*)g_vpart[0];
    const float4* p1 = (const float4*)g_vpart[1];
    float4 a = p0[idx], b = p1[idx];
    float4 s = make_float4(a.x + b.x, a.y + b.y, a.z + b.z, a.w + b.w);
    uint32_t h01, h23, l01, l23;
    split4(s, h01, h23, l01, l23);
    *(uint2*)&g_vhi[(size_t)idx * 4] = make_uint2(h01, h23);
    *(uint2*)&g_vlo[(size_t)idx * 4] = make_uint2(l01, l23);
}

// ---------------------------------------------------------------------------
// k_gemm2: y = v @ out_core^T. Tile 128x128, K=64 one shot, warp tile 64x32.
// smem: AH@0 AL@18432 BH@36864 BL@55296 (128 rows x 144B each) = 73728B.
// ---------------------------------------------------------------------------
#define G2_SMEM 73728

__global__ __launch_bounds__(256) void k_gemm2(float* __restrict__ y) {
    extern __shared__ char sm[];
    const uint32_t sb = smem_u32(sm);
    const int tid = threadIdx.x, warp = tid >> 5, lane = tid & 31;
    const int gr = lane >> 2, p = lane & 3;
    const int n0b = blockIdx.x * 128, m0b = blockIdx.y * 128;

    {   // cp.async all 4 tiles
        const int row = tid >> 1, q = (tid & 1) * 4;
        const uint32_t drow = sb + row * RSTR;
        const __nv_bfloat16* sa = g_vhi  + (size_t)(m0b + row) * 64;
        const __nv_bfloat16* sal = g_vlo + (size_t)(m0b + row) * 64;
        const __nv_bfloat16* sbh = g_ochi + (size_t)(n0b + row) * 64;
        const __nv_bfloat16* sbl = g_oclo + (size_t)(n0b + row) * 64;
#pragma unroll
        for (int j = 0; j < 4; j++) {
            cpa16(drow + (q + j) * 16,         sa  + (q + j) * 8);
            cpa16(drow + 18432 + (q + j) * 16, sal + (q + j) * 8);
            cpa16(drow + 36864 + (q + j) * 16, sbh + (q + j) * 8);
            cpa16(drow + 55296 + (q + j) * 16, sbl + (q + j) * 8);
        }
    }
    CP_COMMIT();
    CP_WAIT0();
    __syncthreads();

    const int m0 = (warp >> 2) * 64, n0 = (warp & 3) * 32;
    const int lr = (lane & 7) + ((lane >> 3) & 1) * 8;
    const int lk = (lane >> 4) * 16;
    const uint32_t offA = (uint32_t)((m0 + lr) * RSTR + lk);
    const uint32_t offB = (uint32_t)((n0 + lr) * RSTR + lk);

    float acc[4][4][4];
#pragma unroll
    for (int mt = 0; mt < 4; mt++)
#pragma unroll
        for (int nt = 0; nt < 4; nt++)
            acc[mt][nt][0] = acc[mt][nt][1] = acc[mt][nt][2] = acc[mt][nt][3] = 0.f;

#pragma unroll
    for (int ks = 0; ks < 4; ks++) {
        const uint32_t ka = ks * 32;
        uint32_t Ah[4][4], Al[4][4], B0[4], B1[4], L0[4], L1[4];
#pragma unroll
        for (int mt = 0; mt < 4; mt++)
            ldsm4(Ah[mt], sb + offA + mt * 16 * RSTR + ka);
        ldsm4(B0, sb + 36864 + offB + ka);
        ldsm4(B1, sb + 36864 + 16 * RSTR + offB + ka);
        // hi*hi
#pragma unroll
        for (int mt = 0; mt < 4; mt++) {
            mma16816(acc[mt][0], Ah[mt][0], Ah[mt][1], Ah[mt][2], Ah[mt][3], B0[0], B0[2]);
            mma16816(acc[mt][1], Ah[mt][0], Ah[mt][1], Ah[mt][2], Ah[mt][3], B0[1], B0[3]);
            mma16816(acc[mt][2], Ah[mt][0], Ah[mt][1], Ah[mt][2], Ah[mt][3], B1[0], B1[2]);
            mma16816(acc[mt][3], Ah[mt][0], Ah[mt][1], Ah[mt][2], Ah[mt][3], B1[1], B1[3]);
        }
        // hi*lo
        ldsm4(L0, sb + 55296 + offB + ka);
        ldsm4(L1, sb + 55296 + 16 * RSTR + offB + ka);
#pragma unroll
        for (int mt = 0; mt < 4; mt++) {
            mma16816(acc[mt][0], Ah[mt][0], Ah[mt][1], Ah[mt][2], Ah[mt][3], L0[0], L0[2]);
            mma16816(acc[mt][1], Ah[mt][0], Ah[mt][1], Ah[mt][2], Ah[mt][3], L0[1], L0[3]);
            mma16816(acc[mt][2], Ah[mt][0], Ah[mt][1], Ah[mt][2], Ah[mt][3], L1[0], L1[2]);
            mma16816(acc[mt][3], Ah[mt][0], Ah[mt][1], Ah[mt][2], Ah[mt][3], L1[1], L1[3]);
        }
        // lo*hi
#pragma unroll
        for (int mt = 0; mt < 4; mt++)
            ldsm4(Al[mt], sb + 18432 + offA + mt * 16 * RSTR + ka);
#pragma unroll
        for (int mt = 0; mt < 4; mt++) {
            mma16816(acc[mt][0], Al[mt][0], Al[mt][1], Al[mt][2], Al[mt][3], B0[0], B0[2]);
            mma16816(acc[mt][1], Al[mt][0], Al[mt][1], Al[mt][2], Al[mt][3], B0[1], B0[3]);
            mma16816(acc[mt][2], Al[mt][0], Al[mt][1], Al[mt][2], Al[mt][3], B1[0], B1[2]);
            mma16816(acc[mt][3], Al[mt][0], Al[mt][1], Al[mt][2], Al[mt][3], B1[1], B1[3]);
        }
    }

#pragma unroll
    for (int mt = 0; mt < 4; mt++) {
#pragma unroll
        for (int nt = 0; nt < 4; nt++) {
            const int row = m0b + m0 + mt * 16 + gr;
            const int col = n0b + n0 + nt * 8 + 2 * p;
            *(float2*)&y[(size_t)row * OUT_ + col] =
                make_float2(acc[mt][nt][0], acc[mt][nt][1]);
            *(float2*)&y[(size_t)(row + 8) * OUT_ + col] =
                make_float2(acc[mt][nt][2], acc[mt][nt][3]);
        }
    }
}

// ---------------------------------------------------------------------------
extern "C" void kernel_launch(void* const* d_in, const int* in_sizes, int n_in,
                              void* d_out, int out_size) {
    const float* x        = (const float*)d_in[0];
    const float* tc       = (const float*)d_in[1];
    const float* task     = (const float*)d_in[2];
    const float* in_core  = (const float*)d_in[3];
    const float* out_core = (const float*)d_in[4];
    float* y = (float*)d_out;

    cudaFuncSetAttribute(k_gemm1, cudaFuncAttributeMaxDynamicSharedMemorySize, G1_SMEM);
    cudaFuncSetAttribute(k_gemm2, cudaFuncAttributeMaxDynamicSharedMemorySize, G2_SMEM);

    k_pre1<<<192, 256>>>(task, tc, out_core);
    k_bt<<<128, 256>>>(in_core);
    k_gemm1<<<256, 256, G1_SMEM>>>(x);
    k_vred<<<512, 256>>>();
    k_gemm2<<<dim3(OUT_ / 128, BT_ / 128), 256, G2_SMEM>>>(y);
}